// round 8
// baseline (speedup 1.0000x reference)
#include <cuda_runtime.h>
#include <cuda_bf16.h>
#include <cstdint>

#define NN 50000
#define EE 625000
#define D0 128
#define D1 128
#define D2 64
#define SCAN_B 1024
#define NB ((NN + SCAN_B - 1) / SCAN_B)

// ---- device-global scratch ----
__device__ int   g_degi[NN];
__device__ float g_dinv[NN];
__device__ int   g_off [NN + 1];
__device__ int   g_cur [NN];
__device__ int2  g_edge[EE];
__device__ int   g_bsum [NB];
__device__ int   g_bbase[NB];
__device__ float g_h1  [(size_t)NN * D1];
__device__ float g_h2  [(size_t)NN * D2];

// ---------------------------------------------------------------------------
// Warp MMA helpers
// ---------------------------------------------------------------------------
__device__ __forceinline__ uint32_t smem_u32(const void* p) {
    uint32_t a;
    asm("{ .reg .u64 t; cvta.to.shared.u64 t, %1; cvt.u32.u64 %0, t; }" : "=r"(a) : "l"(p));
    return a;
}
__device__ __forceinline__ void ldsm_x4(uint32_t* r, uint32_t addr) {
    asm volatile("ldmatrix.sync.aligned.m8n8.x4.shared.b16 {%0,%1,%2,%3}, [%4];"
                 : "=r"(r[0]), "=r"(r[1]), "=r"(r[2]), "=r"(r[3]) : "r"(addr));
}
__device__ __forceinline__ void mma_bf16(float* d, const uint32_t* a, const uint32_t* b) {
    asm volatile(
        "mma.sync.aligned.m16n8k16.row.col.f32.bf16.bf16.f32 "
        "{%0,%1,%2,%3}, {%4,%5,%6,%7}, {%8,%9}, {%0,%1,%2,%3};"
        : "+f"(d[0]), "+f"(d[1]), "+f"(d[2]), "+f"(d[3])
        : "r"(a[0]), "r"(a[1]), "r"(a[2]), "r"(a[3]), "r"(b[0]), "r"(b[1]));
}
__device__ __forceinline__ void bf16_split(float x, __nv_bfloat16& h, __nv_bfloat16& l) {
    h = __float2bfloat16_rn(x);
    l = __float2bfloat16_rn(x - __bfloat162float(h));
}

// ---------------------------------------------------------------------------
// CSR build
// ---------------------------------------------------------------------------
__global__ void k_count_deg(const int* __restrict__ ei, int E) {
    int e2 = (blockIdx.x * blockDim.x + threadIdx.x) * 2;
    if (e2 + 1 < E) {
        int2 d = *reinterpret_cast<const int2*>(ei + E + e2);
        atomicAdd(&g_degi[d.x], 1);
        atomicAdd(&g_degi[d.y], 1);
    } else if (e2 < E) {
        atomicAdd(&g_degi[ei[E + e2]], 1);
    }
}

__global__ void k_dinv_blockreduce(int N) {
    __shared__ int warp_sum[32];
    int i = blockIdx.x * SCAN_B + threadIdx.x;
    int v = 0;
    if (i < N) {
        v = g_degi[i];
        g_dinv[i] = rsqrtf((float)(v + 1));
    }
    int s = v;
    #pragma unroll
    for (int o = 16; o > 0; o >>= 1) s += __shfl_down_sync(0xffffffffu, s, o);
    if ((threadIdx.x & 31) == 0) warp_sum[threadIdx.x >> 5] = s;
    __syncthreads();
    if (threadIdx.x < 32) {
        int t = (threadIdx.x < (SCAN_B / 32)) ? warp_sum[threadIdx.x] : 0;
        #pragma unroll
        for (int o = 16; o > 0; o >>= 1) t += __shfl_down_sync(0xffffffffu, t, o);
        if (threadIdx.x == 0) g_bsum[blockIdx.x] = t;
    }
}

__global__ void k_scan_bsum(int B) {
    int lane = threadIdx.x;
    int i0 = 2 * lane, i1 = 2 * lane + 1;
    int v0 = (i0 < B) ? g_bsum[i0] : 0;
    int v1 = (i1 < B) ? g_bsum[i1] : 0;
    int p = v0 + v1;
    int s = p;
    #pragma unroll
    for (int o = 1; o < 32; o <<= 1) {
        int u = __shfl_up_sync(0xffffffffu, s, o);
        if (lane >= o) s += u;
    }
    int ex = s - p;
    if (i0 < B) g_bbase[i0] = ex;
    if (i1 < B) g_bbase[i1] = ex + v0;
}

__global__ void k_scan_final(int N, int E) {
    __shared__ int s[SCAN_B];
    int t = threadIdx.x;
    int i = blockIdx.x * SCAN_B + t;
    int v = (i < N) ? g_degi[i] : 0;
    s[t] = v;
    __syncthreads();
    #pragma unroll
    for (int off = 1; off < SCAN_B; off <<= 1) {
        int u = (t >= off) ? s[t - off] : 0;
        __syncthreads();
        s[t] += u;
        __syncthreads();
    }
    if (i < N) {
        int ex = g_bbase[blockIdx.x] + s[t] - v;
        g_off[i] = ex;
        g_cur[i] = ex;
        if (i == N - 1) g_off[N] = E;
    }
}

__global__ void k_fill(const int* __restrict__ ei, int E) {
    int e2 = (blockIdx.x * blockDim.x + threadIdx.x) * 2;
    if (e2 + 1 < E) {
        int2 s = *reinterpret_cast<const int2*>(ei + e2);
        int2 d = *reinterpret_cast<const int2*>(ei + E + e2);
        int p0 = atomicAdd(&g_cur[d.x], 1);
        g_edge[p0] = make_int2(s.x, __float_as_int(g_dinv[s.x] * g_dinv[d.x]));
        int p1 = atomicAdd(&g_cur[d.y], 1);
        g_edge[p1] = make_int2(s.y, __float_as_int(g_dinv[s.y] * g_dinv[d.y]));
    } else if (e2 < E) {
        int s = ei[e2], d = ei[E + e2];
        int p = atomicAdd(&g_cur[d], 1);
        g_edge[p] = make_int2(s, __float_as_int(g_dinv[s] * g_dinv[d]));
    }
}

// ---------------------------------------------------------------------------
// GEMM1 (bf16 hi/lo split, fp32 acc), TM=64, occupancy 2: h1 = x @ W1^T
// ---------------------------------------------------------------------------
__global__ __launch_bounds__(256, 2)
void k_gemm1(const float* __restrict__ A, const float* __restrict__ W,
             float* __restrict__ H, int M)
{
    constexpr int K = 128, TM = 64, NOUT = 128;
    constexpr int LDB = (K + 8) * 2;
    constexpr uint32_t OFF_AHI = 0;
    constexpr uint32_t OFF_ALO = OFF_AHI + TM * LDB;
    constexpr uint32_t OFF_WHI = OFF_ALO + TM * LDB;
    constexpr uint32_t OFF_WLO = OFF_WHI + NOUT * LDB;
    constexpr int MW = 2, WN = 32, NT = 4, NG = 2;

    extern __shared__ char smem[];
    const uint32_t sb = smem_u32(smem);
    const int tid    = threadIdx.x;
    const int wid    = tid >> 5;
    const int lane   = tid & 31;
    const int warp_m = wid & (MW - 1);
    const int warp_n = wid / MW;
    const int row0   = blockIdx.x * TM;

    for (int fid = tid; fid < TM * (K / 4); fid += 256) {
        int r = fid >> 5, k = (fid & 31) * 4;
        int row = row0 + r;
        float4 v = make_float4(0.f, 0.f, 0.f, 0.f);
        if (row < M)
            v = *reinterpret_cast<const float4*>(A + (size_t)row * K + k);
        __nv_bfloat162 h01, h23, l01, l23;
        bf16_split(v.x, h01.x, l01.x); bf16_split(v.y, h01.y, l01.y);
        bf16_split(v.z, h23.x, l23.x); bf16_split(v.w, h23.y, l23.y);
        uint32_t o = (uint32_t)r * LDB + (uint32_t)k * 2;
        *reinterpret_cast<uint2*>(smem + OFF_AHI + o) =
            make_uint2(*reinterpret_cast<uint32_t*>(&h01), *reinterpret_cast<uint32_t*>(&h23));
        *reinterpret_cast<uint2*>(smem + OFF_ALO + o) =
            make_uint2(*reinterpret_cast<uint32_t*>(&l01), *reinterpret_cast<uint32_t*>(&l23));
    }
    for (int fid = tid; fid < NOUT * (K / 4); fid += 256) {
        int c = fid >> 5, k = (fid & 31) * 4;
        float4 v = *reinterpret_cast<const float4*>(W + (size_t)c * K + k);
        __nv_bfloat162 h01, h23, l01, l23;
        bf16_split(v.x, h01.x, l01.x); bf16_split(v.y, h01.y, l01.y);
        bf16_split(v.z, h23.x, l23.x); bf16_split(v.w, h23.y, l23.y);
        uint32_t o = (uint32_t)c * LDB + (uint32_t)k * 2;
        *reinterpret_cast<uint2*>(smem + OFF_WHI + o) =
            make_uint2(*reinterpret_cast<uint32_t*>(&h01), *reinterpret_cast<uint32_t*>(&h23));
        *reinterpret_cast<uint2*>(smem + OFF_WLO + o) =
            make_uint2(*reinterpret_cast<uint32_t*>(&l01), *reinterpret_cast<uint32_t*>(&l23));
    }
    __syncthreads();

    float acc[2][NT][4];
    #pragma unroll
    for (int mt = 0; mt < 2; mt++)
        #pragma unroll
        for (int nt = 0; nt < NT; nt++)
            #pragma unroll
            for (int j = 0; j < 4; j++) acc[mt][nt][j] = 0.f;

    const uint32_t a_roff = (uint32_t)((lane & 7) + ((lane >> 3) & 1) * 8) * LDB
                          + (uint32_t)((lane >> 4) * 8) * 2;
    const uint32_t b_roff = (uint32_t)((lane & 7) + ((lane >> 4) & 1) * 8) * LDB
                          + (uint32_t)(((lane >> 3) & 1) * 8) * 2;

    #pragma unroll
    for (int ks = 0; ks < K / 16; ks++) {
        const uint32_t kb = (uint32_t)(ks * 16) * 2;
        uint32_t ah[2][4], al[2][4];
        #pragma unroll
        for (int mt = 0; mt < 2; mt++) {
            uint32_t base = (uint32_t)(warp_m * 32 + mt * 16) * LDB + kb + a_roff;
            ldsm_x4(ah[mt], sb + OFF_AHI + base);
            ldsm_x4(al[mt], sb + OFF_ALO + base);
        }
        uint32_t bh[NG][4], bl[NG][4];
        #pragma unroll
        for (int g = 0; g < NG; g++) {
            uint32_t base = (uint32_t)(warp_n * WN + g * 16) * LDB + kb + b_roff;
            ldsm_x4(bh[g], sb + OFF_WHI + base);
            ldsm_x4(bl[g], sb + OFF_WLO + base);
        }
        #pragma unroll
        for (int mt = 0; mt < 2; mt++)
            #pragma unroll
            for (int nt = 0; nt < NT; nt++) {
                const uint32_t* ph = &bh[nt >> 1][(nt & 1) * 2];
                const uint32_t* pl = &bl[nt >> 1][(nt & 1) * 2];
                mma_bf16(acc[mt][nt], ah[mt], ph);
                mma_bf16(acc[mt][nt], ah[mt], pl);
                mma_bf16(acc[mt][nt], al[mt], ph);
            }
    }

    #pragma unroll
    for (int mt = 0; mt < 2; mt++) {
        int rbase = row0 + warp_m * 32 + mt * 16 + (lane >> 2);
        #pragma unroll
        for (int hf = 0; hf < 2; hf++) {
            int row = rbase + hf * 8;
            if (row < M) {
                #pragma unroll
                for (int nt = 0; nt < NT; nt++) {
                    int c = warp_n * WN + nt * 8 + (lane & 3) * 2;
                    float2 hv = make_float2(acc[mt][nt][hf * 2 + 0], acc[mt][nt][hf * 2 + 1]);
                    *reinterpret_cast<float2*>(H + (size_t)row * NOUT + c) = hv;
                }
            }
        }
    }
}

// ---------------------------------------------------------------------------
// FUSED gather128 + gemm2:
//   per row: a = dinv^2*h1[node] + sum coef*h1[src]  (CSR walk, registers)
//            A'row = relu(a + b1) -> bf16 hi/lo smem tile
//   then MMA 128x64x128; epilogue h2 = acc, out = dinv^2*acc + b2
// ---------------------------------------------------------------------------
#define EDGE_FMA(a, e)                                                            \
    {                                                                             \
        float c_ = __int_as_float((e).y);                                         \
        const float4 v_ = *reinterpret_cast<const float4*>(                       \
            h1 + (size_t)(e).x * 128 + lane4);                                    \
        (a).x = fmaf(c_, v_.x, (a).x); (a).y = fmaf(c_, v_.y, (a).y);             \
        (a).z = fmaf(c_, v_.z, (a).z); (a).w = fmaf(c_, v_.w, (a).w);             \
    }

__global__ __launch_bounds__(256, 2)
void k_fused_g2(const float* __restrict__ h1, const float* __restrict__ W,
                const float* __restrict__ b1, const float* __restrict__ b2,
                float* __restrict__ H2, float* __restrict__ OUT, int N)
{
    constexpr int K = 128, TM = 128, NOUT = 64;
    constexpr int LDB = (K + 8) * 2;
    constexpr uint32_t OFF_AHI = 0;
    constexpr uint32_t OFF_ALO = OFF_AHI + TM * LDB;
    constexpr uint32_t OFF_WHI = OFF_ALO + TM * LDB;
    constexpr uint32_t OFF_WLO = OFF_WHI + NOUT * LDB;
    constexpr int MW = 4, WN = 32, NT = 4, NG = 2;

    extern __shared__ char smem[];
    const uint32_t sb = smem_u32(smem);
    const int tid   = threadIdx.x;
    const int wid   = tid >> 5;
    const int lane  = tid & 31;
    const int lane4 = lane * 4;
    const int row0  = blockIdx.x * TM;

    // ---- W2 convert (64 x 128)
    for (int fid = tid; fid < NOUT * (K / 4); fid += 256) {
        int c = fid >> 5, k = (fid & 31) * 4;
        float4 v = *reinterpret_cast<const float4*>(W + (size_t)c * K + k);
        __nv_bfloat162 h01, h23, l01, l23;
        bf16_split(v.x, h01.x, l01.x); bf16_split(v.y, h01.y, l01.y);
        bf16_split(v.z, h23.x, l23.x); bf16_split(v.w, h23.y, l23.y);
        uint32_t o = (uint32_t)c * LDB + (uint32_t)k * 2;
        *reinterpret_cast<uint2*>(smem + OFF_WHI + o) =
            make_uint2(*reinterpret_cast<uint32_t*>(&h01), *reinterpret_cast<uint32_t*>(&h23));
        *reinterpret_cast<uint2*>(smem + OFF_WLO + o) =
            make_uint2(*reinterpret_cast<uint32_t*>(&l01), *reinterpret_cast<uint32_t*>(&l23));
    }

    // ---- gather phase: warp handles rows wid, wid+8, ... (16 rows)
    const float4 bb = *reinterpret_cast<const float4*>(b1 + lane4);
    for (int r = wid; r < TM; r += 8) {
        int node = row0 + r;
        float4 a0 = make_float4(0.f, 0.f, 0.f, 0.f);
        if (node < N) {
            int beg = g_off[node], end = g_off[node + 1];
            float s = g_dinv[node]; s = s * s;
            float4 hs = *reinterpret_cast<const float4*>(h1 + (size_t)node * 128 + lane4);
            a0 = make_float4(s * hs.x, s * hs.y, s * hs.z, s * hs.w);
            float4 a1 = make_float4(0.f, 0.f, 0.f, 0.f);
            float4 a2 = make_float4(0.f, 0.f, 0.f, 0.f);
            float4 a3 = make_float4(0.f, 0.f, 0.f, 0.f);
            int j = beg;
            for (; j + 3 < end; j += 4) {
                int2 e0 = __ldg(&g_edge[j + 0]);
                int2 e1 = __ldg(&g_edge[j + 1]);
                int2 e2 = __ldg(&g_edge[j + 2]);
                int2 e3 = __ldg(&g_edge[j + 3]);
                EDGE_FMA(a0, e0) EDGE_FMA(a1, e1) EDGE_FMA(a2, e2) EDGE_FMA(a3, e3)
            }
            for (; j < end; j++) {
                int2 e0 = __ldg(&g_edge[j]);
                EDGE_FMA(a0, e0)
            }
            a0.x = fmaxf(a0.x + a1.x + a2.x + a3.x + bb.x, 0.f);
            a0.y = fmaxf(a0.y + a1.y + a2.y + a3.y + bb.y, 0.f);
            a0.z = fmaxf(a0.z + a1.z + a2.z + a3.z + bb.z, 0.f);
            a0.w = fmaxf(a0.w + a1.w + a2.w + a3.w + bb.w, 0.f);
        }
        __nv_bfloat162 h01, h23, l01, l23;
        bf16_split(a0.x, h01.x, l01.x); bf16_split(a0.y, h01.y, l01.y);
        bf16_split(a0.z, h23.x, l23.x); bf16_split(a0.w, h23.y, l23.y);
        uint32_t o = (uint32_t)r * LDB + (uint32_t)lane4 * 2;
        *reinterpret_cast<uint2*>(smem + OFF_AHI + o) =
            make_uint2(*reinterpret_cast<uint32_t*>(&h01), *reinterpret_cast<uint32_t*>(&h23));
        *reinterpret_cast<uint2*>(smem + OFF_ALO + o) =
            make_uint2(*reinterpret_cast<uint32_t*>(&l01), *reinterpret_cast<uint32_t*>(&l23));
    }
    __syncthreads();

    // ---- MMA phase (TM=128, NOUT=64): warp_m = wid&3, warp_n = wid>>2
    const int warp_m = wid & (MW - 1);
    const int warp_n = wid / MW;

    float acc[2][NT][4];
    #pragma unroll
    for (int mt = 0; mt < 2; mt++)
        #pragma unroll
        for (int nt = 0; nt < NT; nt++)
            #pragma unroll
            for (int j = 0; j < 4; j++) acc[mt][nt][j] = 0.f;

    const uint32_t a_roff = (uint32_t)((lane & 7) + ((lane >> 3) & 1) * 8) * LDB
                          + (uint32_t)((lane >> 4) * 8) * 2;
    const uint32_t b_roff = (uint32_t)((lane & 7) + ((lane >> 4) & 1) * 8) * LDB
                          + (uint32_t)(((lane >> 3) & 1) * 8) * 2;

    #pragma unroll
    for (int ks = 0; ks < K / 16; ks++) {
        const uint32_t kb = (uint32_t)(ks * 16) * 2;
        uint32_t ah[2][4], al[2][4];
        #pragma unroll
        for (int mt = 0; mt < 2; mt++) {
            uint32_t base = (uint32_t)(warp_m * 32 + mt * 16) * LDB + kb + a_roff;
            ldsm_x4(ah[mt], sb + OFF_AHI + base);
            ldsm_x4(al[mt], sb + OFF_ALO + base);
        }
        uint32_t bh[NG][4], bl[NG][4];
        #pragma unroll
        for (int g = 0; g < NG; g++) {
            uint32_t base = (uint32_t)(warp_n * WN + g * 16) * LDB + kb + b_roff;
            ldsm_x4(bh[g], sb + OFF_WHI + base);
            ldsm_x4(bl[g], sb + OFF_WLO + base);
        }
        #pragma unroll
        for (int mt = 0; mt < 2; mt++)
            #pragma unroll
            for (int nt = 0; nt < NT; nt++) {
                const uint32_t* ph = &bh[nt >> 1][(nt & 1) * 2];
                const uint32_t* pl = &bl[nt >> 1][(nt & 1) * 2];
                mma_bf16(acc[mt][nt], ah[mt], ph);
                mma_bf16(acc[mt][nt], ah[mt], pl);
                mma_bf16(acc[mt][nt], al[mt], ph);
            }
    }

    // ---- epilogue: h2 = acc ; out = dinv^2*acc + b2
    #pragma unroll
    for (int mt = 0; mt < 2; mt++) {
        int rbase = row0 + warp_m * 32 + mt * 16 + (lane >> 2);
        #pragma unroll
        for (int hf = 0; hf < 2; hf++) {
            int row = rbase + hf * 8;
            if (row < N) {
                float s = g_dinv[row]; s = s * s;
                #pragma unroll
                for (int nt = 0; nt < NT; nt++) {
                    int c = warp_n * WN + nt * 8 + (lane & 3) * 2;
                    float2 hv = make_float2(acc[mt][nt][hf * 2 + 0], acc[mt][nt][hf * 2 + 1]);
                    *reinterpret_cast<float2*>(H2 + (size_t)row * NOUT + c) = hv;
                    float2 av;
                    av.x = fmaf(s, hv.x, __ldg(b2 + c + 0));
                    av.y = fmaf(s, hv.y, __ldg(b2 + c + 1));
                    *reinterpret_cast<float2*>(OUT + (size_t)row * NOUT + c) = av;
                }
            }
        }
    }
}

// ---------------------------------------------------------------------------
// Final gather (64-wide): out[dst] += sum coef * h2[src]
// ---------------------------------------------------------------------------
#define EDGE_FMA64(a, e)                                                          \
    {                                                                             \
        float c_ = __int_as_float((e).y);                                         \
        const float4 v_ = *reinterpret_cast<const float4*>(                       \
            H + (size_t)(e).x * 64 + lane4);                                      \
        (a).x = fmaf(c_, v_.x, (a).x); (a).y = fmaf(c_, v_.y, (a).y);             \
        (a).z = fmaf(c_, v_.z, (a).z); (a).w = fmaf(c_, v_.w, (a).w);             \
    }

__global__ void k_gather64(const float* __restrict__ H, float* __restrict__ OUT, int N)
{
    int idx  = blockIdx.x * blockDim.x + threadIdx.x;
    int node = idx >> 4;
    int lane4 = (idx & 15) * 4;
    if (node >= N) return;
    int beg = g_off[node], end = g_off[node + 1];
    float* p = OUT + (size_t)node * 64 + lane4;
    float4 a0 = *reinterpret_cast<const float4*>(p);
    float4 a1 = make_float4(0.f, 0.f, 0.f, 0.f);
    float4 a2 = make_float4(0.f, 0.f, 0.f, 0.f);
    float4 a3 = make_float4(0.f, 0.f, 0.f, 0.f);
    int j = beg;
    for (; j + 3 < end; j += 4) {
        int2 e0 = __ldg(&g_edge[j + 0]);
        int2 e1 = __ldg(&g_edge[j + 1]);
        int2 e2 = __ldg(&g_edge[j + 2]);
        int2 e3 = __ldg(&g_edge[j + 3]);
        EDGE_FMA64(a0, e0) EDGE_FMA64(a1, e1) EDGE_FMA64(a2, e2) EDGE_FMA64(a3, e3)
    }
    for (; j < end; j++) {
        int2 e0 = __ldg(&g_edge[j]);
        EDGE_FMA64(a0, e0)
    }
    a0.x += a1.x + a2.x + a3.x; a0.y += a1.y + a2.y + a3.y;
    a0.z += a1.z + a2.z + a3.z; a0.w += a1.w + a2.w + a3.w;
    *reinterpret_cast<float4*>(p) = a0;
}

// ---------------------------------------------------------------------------
extern "C" void kernel_launch(void* const* d_in, const int* in_sizes, int n_in,
                              void* d_out, int out_size)
{
    const float* x  = (const float*)d_in[0];
    const int*   ei = (const int*)  d_in[1];
    const float* W1 = (const float*)d_in[2];
    const float* b1 = (const float*)d_in[3];
    const float* W2 = (const float*)d_in[4];
    const float* b2 = (const float*)d_in[5];
    float* out = (float*)d_out;

    const int N = in_sizes[0] / D0;
    const int E = in_sizes[1] / 2;

    float *p_h1, *p_h2;
    int   *p_degi;
    cudaGetSymbolAddress((void**)&p_h1,   g_h1);
    cudaGetSymbolAddress((void**)&p_h2,   g_h2);
    cudaGetSymbolAddress((void**)&p_degi, g_degi);

    const int LDBB  = (128 + 8) * 2;
    const int SMEM1 = (64 + 64 + 128 + 128) * LDBB;   // 104448
    const int SMEMF = (128 + 128 + 64 + 64) * LDBB;   // 104448
    cudaFuncSetAttribute(k_gemm1,
                         cudaFuncAttributeMaxDynamicSharedMemorySize, SMEM1);
    cudaFuncSetAttribute(k_fused_g2,
                         cudaFuncAttributeMaxDynamicSharedMemorySize, SMEMF);

    const int nb = (N + SCAN_B - 1) / SCAN_B;

    cudaStream_t s2;
    cudaStreamCreate(&s2);
    cudaEvent_t evF, evCSR;
    cudaEventCreateWithFlags(&evF,   cudaEventDisableTiming);
    cudaEventCreateWithFlags(&evCSR, cudaEventDisableTiming);

    cudaEventRecord(evF, 0);
    cudaStreamWaitEvent(s2, evF, 0);

    // branch B (s2): CSR build
    cudaMemsetAsync(p_degi, 0, (size_t)N * sizeof(int), s2);
    k_count_deg       <<<(E / 2 + 255) / 256, 256, 0, s2>>>(ei, E);
    k_dinv_blockreduce<<<nb, SCAN_B, 0, s2>>>(N);
    k_scan_bsum       <<<1, 32, 0, s2>>>(nb);
    k_scan_final      <<<nb, SCAN_B, 0, s2>>>(N, E);
    k_fill            <<<(E / 2 + 255) / 256, 256, 0, s2>>>(ei, E);
    cudaEventRecord(evCSR, s2);

    // branch A (stream 0): pure GEMM1
    k_gemm1<<<(N + 63) / 64, 256, SMEM1, 0>>>(x, W1, p_h1, N);

    // join, then fused gather+gemm2, then final gather
    cudaStreamWaitEvent(0, evCSR, 0);
    k_fused_g2<<<(N + 127) / 128, 256, SMEMF, 0>>>(p_h1, W2, b1, b2, p_h2, out, N);
    k_gather64<<<(N * 16 + 255) / 256, 256, 0, 0>>>(p_h2, out, N);

    cudaStreamDestroy(s2);
    cudaEventDestroy(evF);
    cudaEventDestroy(evCSR);
}

// round 9
// speedup vs baseline: 1.0644x; 1.0644x over previous
#include <cuda_runtime.h>
#include <cuda_bf16.h>
#include <cstdint>

#define NN 50000
#define EE 625000
#define D0 128
#define D1 128
#define D2 64
#define SCAN_B 1024
#define NB ((NN + SCAN_B - 1) / SCAN_B)

// ---- device-global scratch ----
__device__ int   g_degi[NN];
__device__ float g_dinv[NN];
__device__ int   g_off [NN + 1];
__device__ int   g_cur [NN];
__device__ int2  g_edge[EE];
__device__ int   g_bsum [NB];
__device__ int   g_bbase[NB];
__device__ float g_h1  [(size_t)NN * D1];
__device__ float g_agg1[(size_t)NN * D1];
__device__ float g_h2  [(size_t)NN * D2];

// ---------------------------------------------------------------------------
// Warp MMA helpers
// ---------------------------------------------------------------------------
__device__ __forceinline__ uint32_t smem_u32(const void* p) {
    uint32_t a;
    asm("{ .reg .u64 t; cvta.to.shared.u64 t, %1; cvt.u32.u64 %0, t; }" : "=r"(a) : "l"(p));
    return a;
}
__device__ __forceinline__ void ldsm_x4(uint32_t* r, uint32_t addr) {
    asm volatile("ldmatrix.sync.aligned.m8n8.x4.shared.b16 {%0,%1,%2,%3}, [%4];"
                 : "=r"(r[0]), "=r"(r[1]), "=r"(r[2]), "=r"(r[3]) : "r"(addr));
}
__device__ __forceinline__ void mma_bf16(float* d, const uint32_t* a, const uint32_t* b) {
    asm volatile(
        "mma.sync.aligned.m16n8k16.row.col.f32.bf16.bf16.f32 "
        "{%0,%1,%2,%3}, {%4,%5,%6,%7}, {%8,%9}, {%0,%1,%2,%3};"
        : "+f"(d[0]), "+f"(d[1]), "+f"(d[2]), "+f"(d[3])
        : "r"(a[0]), "r"(a[1]), "r"(a[2]), "r"(a[3]), "r"(b[0]), "r"(b[1]));
}
__device__ __forceinline__ void bf16_split(float x, __nv_bfloat16& h, __nv_bfloat16& l) {
    h = __float2bfloat16_rn(x);
    l = __float2bfloat16_rn(x - __bfloat162float(h));
}

// ---------------------------------------------------------------------------
// CSR build
// ---------------------------------------------------------------------------
__global__ void k_count_deg(const int* __restrict__ ei, int E) {
    int e2 = (blockIdx.x * blockDim.x + threadIdx.x) * 2;
    if (e2 + 1 < E) {
        int2 d = *reinterpret_cast<const int2*>(ei + E + e2);
        atomicAdd(&g_degi[d.x], 1);
        atomicAdd(&g_degi[d.y], 1);
    } else if (e2 < E) {
        atomicAdd(&g_degi[ei[E + e2]], 1);
    }
}

__global__ void k_dinv_blockreduce(int N) {
    __shared__ int warp_sum[32];
    int i = blockIdx.x * SCAN_B + threadIdx.x;
    int v = 0;
    if (i < N) {
        v = g_degi[i];
        g_dinv[i] = rsqrtf((float)(v + 1));
    }
    int s = v;
    #pragma unroll
    for (int o = 16; o > 0; o >>= 1) s += __shfl_down_sync(0xffffffffu, s, o);
    if ((threadIdx.x & 31) == 0) warp_sum[threadIdx.x >> 5] = s;
    __syncthreads();
    if (threadIdx.x < 32) {
        int t = (threadIdx.x < (SCAN_B / 32)) ? warp_sum[threadIdx.x] : 0;
        #pragma unroll
        for (int o = 16; o > 0; o >>= 1) t += __shfl_down_sync(0xffffffffu, t, o);
        if (threadIdx.x == 0) g_bsum[blockIdx.x] = t;
    }
}

__global__ void k_scan_bsum(int B) {
    int lane = threadIdx.x;
    int i0 = 2 * lane, i1 = 2 * lane + 1;
    int v0 = (i0 < B) ? g_bsum[i0] : 0;
    int v1 = (i1 < B) ? g_bsum[i1] : 0;
    int p = v0 + v1;
    int s = p;
    #pragma unroll
    for (int o = 1; o < 32; o <<= 1) {
        int u = __shfl_up_sync(0xffffffffu, s, o);
        if (lane >= o) s += u;
    }
    int ex = s - p;
    if (i0 < B) g_bbase[i0] = ex;
    if (i1 < B) g_bbase[i1] = ex + v0;
}

// warp-shfl block scan (2 barriers instead of 20)
__global__ void k_scan_final(int N, int E) {
    __shared__ int wsum[32];
    int t = threadIdx.x;
    int lane = t & 31, w = t >> 5;
    int i = blockIdx.x * SCAN_B + t;
    int v = (i < N) ? g_degi[i] : 0;
    int s = v;
    #pragma unroll
    for (int o = 1; o < 32; o <<= 1) {
        int u = __shfl_up_sync(0xffffffffu, s, o);
        if (lane >= o) s += u;
    }
    if (lane == 31) wsum[w] = s;
    __syncthreads();
    if (w == 0) {
        int ws = (lane < 32) ? wsum[lane] : 0;
        #pragma unroll
        for (int o = 1; o < 32; o <<= 1) {
            int u = __shfl_up_sync(0xffffffffu, ws, o);
            if (lane >= o) ws += u;
        }
        wsum[lane] = ws;
    }
    __syncthreads();
    int base = (w > 0) ? wsum[w - 1] : 0;
    if (i < N) {
        int ex = g_bbase[blockIdx.x] + base + s - v;   // exclusive
        g_off[i] = ex;
        g_cur[i] = ex;
        if (i == N - 1) g_off[N] = E;
    }
}

__global__ void k_fill(const int* __restrict__ ei, int E) {
    int e2 = (blockIdx.x * blockDim.x + threadIdx.x) * 2;
    if (e2 + 1 < E) {
        int2 s = *reinterpret_cast<const int2*>(ei + e2);
        int2 d = *reinterpret_cast<const int2*>(ei + E + e2);
        int p0 = atomicAdd(&g_cur[d.x], 1);
        g_edge[p0] = make_int2(s.x, __float_as_int(g_dinv[s.x] * g_dinv[d.x]));
        int p1 = atomicAdd(&g_cur[d.y], 1);
        g_edge[p1] = make_int2(s.y, __float_as_int(g_dinv[s.y] * g_dinv[d.y]));
    } else if (e2 < E) {
        int s = ei[e2], d = ei[E + e2];
        int p = atomicAdd(&g_cur[d], 1);
        g_edge[p] = make_int2(s, __float_as_int(g_dinv[s] * g_dinv[d]));
    }
}

// ---------------------------------------------------------------------------
// Tensor-core GEMM (bf16 hi/lo split, fp32 acc), occupancy 2.
// ---------------------------------------------------------------------------
template <int TM, int NOUT, bool IN_ACT, bool OUT_BIAS, bool WRITE_AGG>
__global__ __launch_bounds__(256, 2)
void k_mma_gemm(const float* __restrict__ A, const float* __restrict__ W,
                const float* __restrict__ bin, const float* __restrict__ bout,
                float* __restrict__ H, float* __restrict__ AGG, int M, int row_base)
{
    constexpr int K   = 128;
    constexpr int LDB = (K + 8) * 2;
    constexpr uint32_t OFF_AHI = 0;
    constexpr uint32_t OFF_ALO = OFF_AHI + TM * LDB;
    constexpr uint32_t OFF_WHI = OFF_ALO + TM * LDB;
    constexpr uint32_t OFF_WLO = OFF_WHI + NOUT * LDB;
    constexpr int MW = TM / 32;
    constexpr int NW = 8 / MW;
    constexpr int WN = NOUT / NW;
    constexpr int NT = WN / 8;
    constexpr int NG = NT / 2;

    extern __shared__ char smem[];
    const uint32_t sb = smem_u32(smem);
    const int tid    = threadIdx.x;
    const int wid    = tid >> 5;
    const int lane   = tid & 31;
    const int warp_m = wid & (MW - 1);
    const int warp_n = wid / MW;
    const int row0   = blockIdx.x * TM;

    for (int fid = tid; fid < TM * (K / 4); fid += 256) {
        int r = fid >> 5, k = (fid & 31) * 4;
        int row = row0 + r;
        float4 v = make_float4(0.f, 0.f, 0.f, 0.f);
        if (row < M)
            v = *reinterpret_cast<const float4*>(A + (size_t)row * K + k);
        if (IN_ACT) {
            v.x = fmaxf(v.x + __ldg(bin + k + 0), 0.f);
            v.y = fmaxf(v.y + __ldg(bin + k + 1), 0.f);
            v.z = fmaxf(v.z + __ldg(bin + k + 2), 0.f);
            v.w = fmaxf(v.w + __ldg(bin + k + 3), 0.f);
        }
        __nv_bfloat162 h01, h23, l01, l23;
        bf16_split(v.x, h01.x, l01.x); bf16_split(v.y, h01.y, l01.y);
        bf16_split(v.z, h23.x, l23.x); bf16_split(v.w, h23.y, l23.y);
        uint32_t o = (uint32_t)r * LDB + (uint32_t)k * 2;
        *reinterpret_cast<uint2*>(smem + OFF_AHI + o) =
            make_uint2(*reinterpret_cast<uint32_t*>(&h01), *reinterpret_cast<uint32_t*>(&h23));
        *reinterpret_cast<uint2*>(smem + OFF_ALO + o) =
            make_uint2(*reinterpret_cast<uint32_t*>(&l01), *reinterpret_cast<uint32_t*>(&l23));
    }
    for (int fid = tid; fid < NOUT * (K / 4); fid += 256) {
        int c = fid >> 5, k = (fid & 31) * 4;
        float4 v = *reinterpret_cast<const float4*>(W + (size_t)c * K + k);
        __nv_bfloat162 h01, h23, l01, l23;
        bf16_split(v.x, h01.x, l01.x); bf16_split(v.y, h01.y, l01.y);
        bf16_split(v.z, h23.x, l23.x); bf16_split(v.w, h23.y, l23.y);
        uint32_t o = (uint32_t)c * LDB + (uint32_t)k * 2;
        *reinterpret_cast<uint2*>(smem + OFF_WHI + o) =
            make_uint2(*reinterpret_cast<uint32_t*>(&h01), *reinterpret_cast<uint32_t*>(&h23));
        *reinterpret_cast<uint2*>(smem + OFF_WLO + o) =
            make_uint2(*reinterpret_cast<uint32_t*>(&l01), *reinterpret_cast<uint32_t*>(&l23));
    }
    __syncthreads();

    float acc[2][NT][4];
    #pragma unroll
    for (int mt = 0; mt < 2; mt++)
        #pragma unroll
        for (int nt = 0; nt < NT; nt++)
            #pragma unroll
            for (int j = 0; j < 4; j++) acc[mt][nt][j] = 0.f;

    const uint32_t a_roff = (uint32_t)((lane & 7) + ((lane >> 3) & 1) * 8) * LDB
                          + (uint32_t)((lane >> 4) * 8) * 2;
    const uint32_t b_roff = (uint32_t)((lane & 7) + ((lane >> 4) & 1) * 8) * LDB
                          + (uint32_t)(((lane >> 3) & 1) * 8) * 2;

    #pragma unroll
    for (int ks = 0; ks < K / 16; ks++) {
        const uint32_t kb = (uint32_t)(ks * 16) * 2;
        uint32_t ah[2][4], al[2][4];
        #pragma unroll
        for (int mt = 0; mt < 2; mt++) {
            uint32_t base = (uint32_t)(warp_m * 32 + mt * 16) * LDB + kb + a_roff;
            ldsm_x4(ah[mt], sb + OFF_AHI + base);
            ldsm_x4(al[mt], sb + OFF_ALO + base);
        }
        uint32_t bh[NG][4], bl[NG][4];
        #pragma unroll
        for (int g = 0; g < NG; g++) {
            uint32_t base = (uint32_t)(warp_n * WN + g * 16) * LDB + kb + b_roff;
            ldsm_x4(bh[g], sb + OFF_WHI + base);
            ldsm_x4(bl[g], sb + OFF_WLO + base);
        }
        #pragma unroll
        for (int mt = 0; mt < 2; mt++)
            #pragma unroll
            for (int nt = 0; nt < NT; nt++) {
                const uint32_t* ph = &bh[nt >> 1][(nt & 1) * 2];
                const uint32_t* pl = &bl[nt >> 1][(nt & 1) * 2];
                mma_bf16(acc[mt][nt], ah[mt], ph);
                mma_bf16(acc[mt][nt], ah[mt], pl);
                mma_bf16(acc[mt][nt], al[mt], ph);
            }
    }

    #pragma unroll
    for (int mt = 0; mt < 2; mt++) {
        int rbase = row0 + warp_m * 32 + mt * 16 + (lane >> 2);
        #pragma unroll
        for (int hf = 0; hf < 2; hf++) {
            int row = rbase + hf * 8;
            if (row < M) {
                float s = 0.f;
                if (WRITE_AGG) { s = g_dinv[row_base + row]; s = s * s; }
                #pragma unroll
                for (int nt = 0; nt < NT; nt++) {
                    int c = warp_n * WN + nt * 8 + (lane & 3) * 2;
                    float2 hv = make_float2(acc[mt][nt][hf * 2 + 0], acc[mt][nt][hf * 2 + 1]);
                    *reinterpret_cast<float2*>(H + (size_t)row * NOUT + c) = hv;
                    if (WRITE_AGG) {
                        float2 av;
                        if (OUT_BIAS) {
                            av.x = fmaf(s, hv.x, __ldg(bout + c + 0));
                            av.y = fmaf(s, hv.y, __ldg(bout + c + 1));
                        } else {
                            av = make_float2(s * hv.x, s * hv.y);
                        }
                        *reinterpret_cast<float2*>(AGG + (size_t)row * NOUT + c) = av;
                    }
                }
            }
        }
    }
}

// ---------------------------------------------------------------------------
// CSR gathers (chunked on node range)
// ---------------------------------------------------------------------------
#define EDGE_FMA(a, e, width)                                                     \
    {                                                                             \
        float c_ = __int_as_float((e).y);                                         \
        const float4 v_ = *reinterpret_cast<const float4*>(                       \
            H + (size_t)(e).x * (width) + lane4);                                 \
        (a).x = fmaf(c_, v_.x, (a).x); (a).y = fmaf(c_, v_.y, (a).y);             \
        (a).z = fmaf(c_, v_.z, (a).z); (a).w = fmaf(c_, v_.w, (a).w);             \
    }

__global__ void k_gather128(const float* __restrict__ H, float* __restrict__ AGG,
                            int node_beg, int node_end)
{
    int node = node_beg + blockIdx.x * (blockDim.x >> 5) + (threadIdx.x >> 5);
    int lane4 = (threadIdx.x & 31) * 4;
    if (node >= node_end) return;
    int beg = g_off[node], end = g_off[node + 1];
    float s = g_dinv[node]; s = s * s;
    float4 hs = *reinterpret_cast<const float4*>(H + (size_t)node * 128 + lane4);
    float4 a0 = make_float4(s * hs.x, s * hs.y, s * hs.z, s * hs.w);
    float4 a1 = make_float4(0.f, 0.f, 0.f, 0.f);
    float4 a2 = make_float4(0.f, 0.f, 0.f, 0.f);
    float4 a3 = make_float4(0.f, 0.f, 0.f, 0.f);
    int j = beg;
    for (; j + 3 < end; j += 4) {
        int2 e0 = __ldg(&g_edge[j + 0]);
        int2 e1 = __ldg(&g_edge[j + 1]);
        int2 e2 = __ldg(&g_edge[j + 2]);
        int2 e3 = __ldg(&g_edge[j + 3]);
        EDGE_FMA(a0, e0, 128) EDGE_FMA(a1, e1, 128)
        EDGE_FMA(a2, e2, 128) EDGE_FMA(a3, e3, 128)
    }
    for (; j < end; j++) {
        int2 e0 = __ldg(&g_edge[j]);
        EDGE_FMA(a0, e0, 128)
    }
    a0.x += a1.x + a2.x + a3.x; a0.y += a1.y + a2.y + a3.y;
    a0.z += a1.z + a2.z + a3.z; a0.w += a1.w + a2.w + a3.w;
    *reinterpret_cast<float4*>(AGG + (size_t)node * 128 + lane4) = a0;
}

__global__ void k_gather64(const float* __restrict__ H, float* __restrict__ OUT, int N)
{
    int idx  = blockIdx.x * blockDim.x + threadIdx.x;
    int node = idx >> 4;
    int lane4 = (idx & 15) * 4;
    if (node >= N) return;
    int beg = g_off[node], end = g_off[node + 1];
    float* p = OUT + (size_t)node * 64 + lane4;
    float4 a0 = *reinterpret_cast<const float4*>(p);
    float4 a1 = make_float4(0.f, 0.f, 0.f, 0.f);
    float4 a2 = make_float4(0.f, 0.f, 0.f, 0.f);
    float4 a3 = make_float4(0.f, 0.f, 0.f, 0.f);
    int j = beg;
    for (; j + 3 < end; j += 4) {
        int2 e0 = __ldg(&g_edge[j + 0]);
        int2 e1 = __ldg(&g_edge[j + 1]);
        int2 e2 = __ldg(&g_edge[j + 2]);
        int2 e3 = __ldg(&g_edge[j + 3]);
        EDGE_FMA(a0, e0, 64) EDGE_FMA(a1, e1, 64)
        EDGE_FMA(a2, e2, 64) EDGE_FMA(a3, e3, 64)
    }
    for (; j < end; j++) {
        int2 e0 = __ldg(&g_edge[j]);
        EDGE_FMA(a0, e0, 64)
    }
    a0.x += a1.x + a2.x + a3.x; a0.y += a1.y + a2.y + a3.y;
    a0.z += a1.z + a2.z + a3.z; a0.w += a1.w + a2.w + a3.w;
    *reinterpret_cast<float4*>(p) = a0;
}

// ---------------------------------------------------------------------------
extern "C" void kernel_launch(void* const* d_in, const int* in_sizes, int n_in,
                              void* d_out, int out_size)
{
    const float* x  = (const float*)d_in[0];
    const int*   ei = (const int*)  d_in[1];
    const float* W1 = (const float*)d_in[2];
    const float* b1 = (const float*)d_in[3];
    const float* W2 = (const float*)d_in[4];
    const float* b2 = (const float*)d_in[5];
    float* out = (float*)d_out;

    const int N = in_sizes[0] / D0;
    const int E = in_sizes[1] / 2;

    float *p_h1, *p_agg1, *p_h2;
    int   *p_degi;
    cudaGetSymbolAddress((void**)&p_h1,   g_h1);
    cudaGetSymbolAddress((void**)&p_agg1, g_agg1);
    cudaGetSymbolAddress((void**)&p_h2,   g_h2);
    cudaGetSymbolAddress((void**)&p_degi, g_degi);

    const int LDBB  = (128 + 8) * 2;
    const int SMEM1 = (64 + 64 + D1 + D1) * LDBB;     // 104448 (TM=64)
    const int SMEM2 = (128 + 128 + D2 + D2) * LDBB;   // 104448 (TM=128)
    cudaFuncSetAttribute(k_mma_gemm<64, D1, false, false, false>,
                         cudaFuncAttributeMaxDynamicSharedMemorySize, SMEM1);
    cudaFuncSetAttribute(k_mma_gemm<128, D2, true, true, true>,
                         cudaFuncAttributeMaxDynamicSharedMemorySize, SMEM2);

    const int nb = (N + SCAN_B - 1) / SCAN_B;

    cudaStream_t s2;
    cudaStreamCreate(&s2);
    cudaEvent_t evF, evCSR, evG1, evB;
    cudaEventCreateWithFlags(&evF,   cudaEventDisableTiming);
    cudaEventCreateWithFlags(&evCSR, cudaEventDisableTiming);
    cudaEventCreateWithFlags(&evG1,  cudaEventDisableTiming);
    cudaEventCreateWithFlags(&evB,   cudaEventDisableTiming);

    cudaEventRecord(evF, 0);
    cudaStreamWaitEvent(s2, evF, 0);

    // branch B (s2): CSR build
    cudaMemsetAsync(p_degi, 0, (size_t)N * sizeof(int), s2);
    k_count_deg       <<<(E / 2 + 255) / 256, 256, 0, s2>>>(ei, E);
    k_dinv_blockreduce<<<nb, SCAN_B, 0, s2>>>(N);
    k_scan_bsum       <<<1, 32, 0, s2>>>(nb);
    k_scan_final      <<<nb, SCAN_B, 0, s2>>>(N, E);
    k_fill            <<<(E / 2 + 255) / 256, 256, 0, s2>>>(ei, E);
    cudaEventRecord(evCSR, s2);

    // branch A (stream 0): pure GEMM1 (TM=64, occupancy 2)
    k_mma_gemm<64, D1, false, false, false><<<(N + 63) / 64, 256, SMEM1, 0>>>(
        x, W1, nullptr, nullptr, p_h1, nullptr, N, 0);
    cudaEventRecord(evG1, 0);

    // join both ways for the chunked tail
    cudaStreamWaitEvent(0, evCSR, 0);
    cudaStreamWaitEvent(s2, evG1, 0);

    // 4-chunk tail alternating across the two streams
    const int CH = 4;
    int cbeg[CH + 1];
    for (int c = 0; c <= CH; c++) {
        int b = (int)(((long long)N * c) / CH);
        cbeg[c] = (b + 127) & ~127;          // 128-aligned chunk starts
        if (cbeg[c] > N) cbeg[c] = N;
    }
    cbeg[CH] = N;
    for (int c = 0; c < CH; c++) {
        cudaStream_t st = (c & 1) ? s2 : (cudaStream_t)0;
        int nb_ = cbeg[c], ne_ = cbeg[c + 1], nn = ne_ - nb_;
        if (nn <= 0) continue;
        k_gather128<<<(nn + 7) / 8, 256, 0, st>>>(p_h1, p_agg1, nb_, ne_);
        k_mma_gemm<128, D2, true, true, true><<<(nn + 127) / 128, 256, SMEM2, st>>>(
            p_agg1 + (size_t)nb_ * D1, W2, b1, b2,
            p_h2 + (size_t)nb_ * D2, out + (size_t)nb_ * D2, nn, nb_);
    }
    cudaEventRecord(evB, s2);

    cudaStreamWaitEvent(0, evB, 0);
    k_gather64<<<(N * 16 + 255) / 256, 256, 0, 0>>>(p_h2, out, N);

    cudaStreamDestroy(s2);
    cudaEventDestroy(evF);
    cudaEventDestroy(evCSR);
    cudaEventDestroy(evG1);
    cudaEventDestroy(evB);
}

// round 13
// speedup vs baseline: 1.0978x; 1.0314x over previous
#include <cuda_runtime.h>
#include <cuda_bf16.h>
#include <cstdint>

#define NN 50000
#define EE 625000
#define D0 128
#define D1 128
#define D2 64
#define SCAN_B 1024
#define NB ((NN + SCAN_B - 1) / SCAN_B)

// ---- device-global scratch ----
__device__ int   g_degi[NN];
__device__ float g_dinv[NN];
__device__ int   g_off [NN + 1];
__device__ int   g_cur [NN];
__device__ int2  g_edge[EE];
__device__ int   g_bsum [NB];
__device__ int   g_bbase[NB];
__device__ float g_h1  [(size_t)NN * D1];
__device__ float g_agg1[(size_t)NN * D1];
__device__ float g_h2  [(size_t)NN * D2];

// ---------------------------------------------------------------------------
// Warp MMA helpers
// ---------------------------------------------------------------------------
__device__ __forceinline__ uint32_t smem_u32(const void* p) {
    uint32_t a;
    asm("{ .reg .u64 t; cvta.to.shared.u64 t, %1; cvt.u32.u64 %0, t; }" : "=r"(a) : "l"(p));
    return a;
}
__device__ __forceinline__ void ldsm_x4(uint32_t* r, uint32_t addr) {
    asm volatile("ldmatrix.sync.aligned.m8n8.x4.shared.b16 {%0,%1,%2,%3}, [%4];"
                 : "=r"(r[0]), "=r"(r[1]), "=r"(r[2]), "=r"(r[3]) : "r"(addr));
}
__device__ __forceinline__ void mma_bf16(float* d, const uint32_t* a, const uint32_t* b) {
    asm volatile(
        "mma.sync.aligned.m16n8k16.row.col.f32.bf16.bf16.f32 "
        "{%0,%1,%2,%3}, {%4,%5,%6,%7}, {%8,%9}, {%0,%1,%2,%3};"
        : "+f"(d[0]), "+f"(d[1]), "+f"(d[2]), "+f"(d[3])
        : "r"(a[0]), "r"(a[1]), "r"(a[2]), "r"(a[3]), "r"(b[0]), "r"(b[1]));
}
__device__ __forceinline__ void bf16_split(float x, __nv_bfloat16& h, __nv_bfloat16& l) {
    h = __float2bfloat16_rn(x);
    l = __float2bfloat16_rn(x - __bfloat162float(h));
}

// ---------------------------------------------------------------------------
// CSR build
// ---------------------------------------------------------------------------
__global__ void k_count_deg(const int* __restrict__ ei, int E) {
    int e2 = (blockIdx.x * blockDim.x + threadIdx.x) * 2;
    if (e2 + 1 < E) {
        int2 d = *reinterpret_cast<const int2*>(ei + E + e2);
        atomicAdd(&g_degi[d.x], 1);
        atomicAdd(&g_degi[d.y], 1);
    } else if (e2 < E) {
        atomicAdd(&g_degi[ei[E + e2]], 1);
    }
}

__global__ void k_dinv_blockreduce(int N) {
    __shared__ int warp_sum[32];
    int i = blockIdx.x * SCAN_B + threadIdx.x;
    int v = 0;
    if (i < N) {
        v = g_degi[i];
        g_dinv[i] = rsqrtf((float)(v + 1));
    }
    int s = v;
    #pragma unroll
    for (int o = 16; o > 0; o >>= 1) s += __shfl_down_sync(0xffffffffu, s, o);
    if ((threadIdx.x & 31) == 0) warp_sum[threadIdx.x >> 5] = s;
    __syncthreads();
    if (threadIdx.x < 32) {
        int t = (threadIdx.x < (SCAN_B / 32)) ? warp_sum[threadIdx.x] : 0;
        #pragma unroll
        for (int o = 16; o > 0; o >>= 1) t += __shfl_down_sync(0xffffffffu, t, o);
        if (threadIdx.x == 0) g_bsum[blockIdx.x] = t;
    }
}

__global__ void k_scan_bsum(int B) {
    int lane = threadIdx.x;
    int i0 = 2 * lane, i1 = 2 * lane + 1;
    int v0 = (i0 < B) ? g_bsum[i0] : 0;
    int v1 = (i1 < B) ? g_bsum[i1] : 0;
    int p = v0 + v1;
    int s = p;
    #pragma unroll
    for (int o = 1; o < 32; o <<= 1) {
        int u = __shfl_up_sync(0xffffffffu, s, o);
        if (lane >= o) s += u;
    }
    int ex = s - p;
    if (i0 < B) g_bbase[i0] = ex;
    if (i1 < B) g_bbase[i1] = ex + v0;
}

// warp-shfl block scan (2 barriers)
__global__ void k_scan_final(int N, int E) {
    __shared__ int wsum[32];
    int t = threadIdx.x;
    int lane = t & 31, w = t >> 5;
    int i = blockIdx.x * SCAN_B + t;
    int v = (i < N) ? g_degi[i] : 0;
    int s = v;
    #pragma unroll
    for (int o = 1; o < 32; o <<= 1) {
        int u = __shfl_up_sync(0xffffffffu, s, o);
        if (lane >= o) s += u;
    }
    if (lane == 31) wsum[w] = s;
    __syncthreads();
    if (w == 0) {
        int ws = wsum[lane];
        #pragma unroll
        for (int o = 1; o < 32; o <<= 1) {
            int u = __shfl_up_sync(0xffffffffu, ws, o);
            if (lane >= o) ws += u;
        }
        wsum[lane] = ws;
    }
    __syncthreads();
    int base = (w > 0) ? wsum[w - 1] : 0;
    if (i < N) {
        int ex = g_bbase[blockIdx.x] + base + s - v;
        g_off[i] = ex;
        g_cur[i] = ex;
        if (i == N - 1) g_off[N] = E;
    }
}

__global__ void k_fill(const int* __restrict__ ei, int E) {
    int e2 = (blockIdx.x * blockDim.x + threadIdx.x) * 2;
    if (e2 + 1 < E) {
        int2 s = *reinterpret_cast<const int2*>(ei + e2);
        int2 d = *reinterpret_cast<const int2*>(ei + E + e2);
        int p0 = atomicAdd(&g_cur[d.x], 1);
        g_edge[p0] = make_int2(s.x, __float_as_int(g_dinv[s.x] * g_dinv[d.x]));
        int p1 = atomicAdd(&g_cur[d.y], 1);
        g_edge[p1] = make_int2(s.y, __float_as_int(g_dinv[s.y] * g_dinv[d.y]));
    } else if (e2 < E) {
        int s = ei[e2], d = ei[E + e2];
        int p = atomicAdd(&g_cur[d], 1);
        g_edge[p] = make_int2(s, __float_as_int(g_dinv[s] * g_dinv[d]));
    }
}

// ---------------------------------------------------------------------------
// Tensor-core GEMM (bf16 hi/lo split, fp32 acc), occupancy 2.
// ---------------------------------------------------------------------------
template <int TM, int NOUT, bool IN_ACT, bool OUT_BIAS, bool WRITE_AGG>
__global__ __launch_bounds__(256, 2)
void k_mma_gemm(const float* __restrict__ A, const float* __restrict__ W,
                const float* __restrict__ bin, const float* __restrict__ bout,
                float* __restrict__ H, float* __restrict__ AGG, int M, int row_base)
{
    constexpr int K   = 128;
    constexpr int LDB = (K + 8) * 2;
    constexpr uint32_t OFF_AHI = 0;
    constexpr uint32_t OFF_ALO = OFF_AHI + TM * LDB;
    constexpr uint32_t OFF_WHI = OFF_ALO + TM * LDB;
    constexpr uint32_t OFF_WLO = OFF_WHI + NOUT * LDB;
    constexpr int MW = TM / 32;
    constexpr int NW = 8 / MW;
    constexpr int WN = NOUT / NW;
    constexpr int NT = WN / 8;
    constexpr int NG = NT / 2;

    extern __shared__ char smem[];
    const uint32_t sb = smem_u32(smem);
    const int tid    = threadIdx.x;
    const int wid    = tid >> 5;
    const int lane   = tid & 31;
    const int warp_m = wid & (MW - 1);
    const int warp_n = wid / MW;
    const int row0   = blockIdx.x * TM;

    for (int fid = tid; fid < TM * (K / 4); fid += 256) {
        int r = fid >> 5, k = (fid & 31) * 4;
        int row = row0 + r;
        float4 v = make_float4(0.f, 0.f, 0.f, 0.f);
        if (row < M)
            v = *reinterpret_cast<const float4*>(A + (size_t)row * K + k);
        if (IN_ACT) {
            v.x = fmaxf(v.x + __ldg(bin + k + 0), 0.f);
            v.y = fmaxf(v.y + __ldg(bin + k + 1), 0.f);
            v.z = fmaxf(v.z + __ldg(bin + k + 2), 0.f);
            v.w = fmaxf(v.w + __ldg(bin + k + 3), 0.f);
        }
        __nv_bfloat162 h01, h23, l01, l23;
        bf16_split(v.x, h01.x, l01.x); bf16_split(v.y, h01.y, l01.y);
        bf16_split(v.z, h23.x, l23.x); bf16_split(v.w, h23.y, l23.y);
        uint32_t o = (uint32_t)r * LDB + (uint32_t)k * 2;
        *reinterpret_cast<uint2*>(smem + OFF_AHI + o) =
            make_uint2(*reinterpret_cast<uint32_t*>(&h01), *reinterpret_cast<uint32_t*>(&h23));
        *reinterpret_cast<uint2*>(smem + OFF_ALO + o) =
            make_uint2(*reinterpret_cast<uint32_t*>(&l01), *reinterpret_cast<uint32_t*>(&l23));
    }
    for (int fid = tid; fid < NOUT * (K / 4); fid += 256) {
        int c = fid >> 5, k = (fid & 31) * 4;
        float4 v = *reinterpret_cast<const float4*>(W + (size_t)c * K + k);
        __nv_bfloat162 h01, h23, l01, l23;
        bf16_split(v.x, h01.x, l01.x); bf16_split(v.y, h01.y, l01.y);
        bf16_split(v.z, h23.x, l23.x); bf16_split(v.w, h23.y, l23.y);
        uint32_t o = (uint32_t)c * LDB + (uint32_t)k * 2;
        *reinterpret_cast<uint2*>(smem + OFF_WHI + o) =
            make_uint2(*reinterpret_cast<uint32_t*>(&h01), *reinterpret_cast<uint32_t*>(&h23));
        *reinterpret_cast<uint2*>(smem + OFF_WLO + o) =
            make_uint2(*reinterpret_cast<uint32_t*>(&l01), *reinterpret_cast<uint32_t*>(&l23));
    }
    __syncthreads();

    float acc[2][NT][4];
    #pragma unroll
    for (int mt = 0; mt < 2; mt++)
        #pragma unroll
        for (int nt = 0; nt < NT; nt++)
            #pragma unroll
            for (int j = 0; j < 4; j++) acc[mt][nt][j] = 0.f;

    const uint32_t a_roff = (uint32_t)((lane & 7) + ((lane >> 3) & 1) * 8) * LDB
                          + (uint32_t)((lane >> 4) * 8) * 2;
    const uint32_t b_roff = (uint32_t)((lane & 7) + ((lane >> 4) & 1) * 8) * LDB
                          + (uint32_t)(((lane >> 3) & 1) * 8) * 2;

    #pragma unroll
    for (int ks = 0; ks < K / 16; ks++) {
        const uint32_t kb = (uint32_t)(ks * 16) * 2;
        uint32_t ah[2][4], al[2][4];
        #pragma unroll
        for (int mt = 0; mt < 2; mt++) {
            uint32_t base = (uint32_t)(warp_m * 32 + mt * 16) * LDB + kb + a_roff;
            ldsm_x4(ah[mt], sb + OFF_AHI + base);
            ldsm_x4(al[mt], sb + OFF_ALO + base);
        }
        uint32_t bh[NG][4], bl[NG][4];
        #pragma unroll
        for (int g = 0; g < NG; g++) {
            uint32_t base = (uint32_t)(warp_n * WN + g * 16) * LDB + kb + b_roff;
            ldsm_x4(bh[g], sb + OFF_WHI + base);
            ldsm_x4(bl[g], sb + OFF_WLO + base);
        }
        #pragma unroll
        for (int mt = 0; mt < 2; mt++)
            #pragma unroll
            for (int nt = 0; nt < NT; nt++) {
                const uint32_t* ph = &bh[nt >> 1][(nt & 1) * 2];
                const uint32_t* pl = &bl[nt >> 1][(nt & 1) * 2];
                mma_bf16(acc[mt][nt], ah[mt], ph);
                mma_bf16(acc[mt][nt], ah[mt], pl);
                mma_bf16(acc[mt][nt], al[mt], ph);
            }
    }

    #pragma unroll
    for (int mt = 0; mt < 2; mt++) {
        int rbase = row0 + warp_m * 32 + mt * 16 + (lane >> 2);
        #pragma unroll
        for (int hf = 0; hf < 2; hf++) {
            int row = rbase + hf * 8;
            if (row < M) {
                float s = 0.f;
                if (WRITE_AGG) { s = g_dinv[row_base + row]; s = s * s; }
                #pragma unroll
                for (int nt = 0; nt < NT; nt++) {
                    int c = warp_n * WN + nt * 8 + (lane & 3) * 2;
                    float2 hv = make_float2(acc[mt][nt][hf * 2 + 0], acc[mt][nt][hf * 2 + 1]);
                    *reinterpret_cast<float2*>(H + (size_t)row * NOUT + c) = hv;
                    if (WRITE_AGG) {
                        float2 av;
                        if (OUT_BIAS) {
                            av.x = fmaf(s, hv.x, __ldg(bout + c + 0));
                            av.y = fmaf(s, hv.y, __ldg(bout + c + 1));
                        } else {
                            av = make_float2(s * hv.x, s * hv.y);
                        }
                        *reinterpret_cast<float2*>(AGG + (size_t)row * NOUT + c) = av;
                    }
                }
            }
        }
    }
}

// ---------------------------------------------------------------------------
// CSR gathers (chunked on node range)
// ---------------------------------------------------------------------------
#define EDGE_FMA(a, e, width)                                                     \
    {                                                                             \
        float c_ = __int_as_float((e).y);                                         \
        const float4 v_ = *reinterpret_cast<const float4*>(                       \
            H + (size_t)(e).x * (width) + lane4);                                 \
        (a).x = fmaf(c_, v_.x, (a).x); (a).y = fmaf(c_, v_.y, (a).y);             \
        (a).z = fmaf(c_, v_.z, (a).z); (a).w = fmaf(c_, v_.w, (a).w);             \
    }

__global__ void k_gather128(const float* __restrict__ H, float* __restrict__ AGG,
                            int node_beg, int node_end)
{
    int node = node_beg + blockIdx.x * (blockDim.x >> 5) + (threadIdx.x >> 5);
    int lane4 = (threadIdx.x & 31) * 4;
    if (node >= node_end) return;
    int beg = g_off[node], end = g_off[node + 1];
    float s = g_dinv[node]; s = s * s;
    float4 hs = *reinterpret_cast<const float4*>(H + (size_t)node * 128 + lane4);
    float4 a0 = make_float4(s * hs.x, s * hs.y, s * hs.z, s * hs.w);
    float4 a1 = make_float4(0.f, 0.f, 0.f, 0.f);
    float4 a2 = make_float4(0.f, 0.f, 0.f, 0.f);
    float4 a3 = make_float4(0.f, 0.f, 0.f, 0.f);
    int j = beg;
    for (; j + 3 < end; j += 4) {
        int2 e0 = __ldg(&g_edge[j + 0]);
        int2 e1 = __ldg(&g_edge[j + 1]);
        int2 e2 = __ldg(&g_edge[j + 2]);
        int2 e3 = __ldg(&g_edge[j + 3]);
        EDGE_FMA(a0, e0, 128) EDGE_FMA(a1, e1, 128)
        EDGE_FMA(a2, e2, 128) EDGE_FMA(a3, e3, 128)
    }
    for (; j < end; j++) {
        int2 e0 = __ldg(&g_edge[j]);
        EDGE_FMA(a0, e0, 128)
    }
    a0.x += a1.x + a2.x + a3.x; a0.y += a1.y + a2.y + a3.y;
    a0.z += a1.z + a2.z + a3.z; a0.w += a1.w + a2.w + a3.w;
    *reinterpret_cast<float4*>(AGG + (size_t)node * 128 + lane4) = a0;
}

__global__ void k_gather64(const float* __restrict__ H, float* __restrict__ OUT, int N)
{
    int idx  = blockIdx.x * blockDim.x + threadIdx.x;
    int node = idx >> 4;
    int lane4 = (idx & 15) * 4;
    if (node >= N) return;
    int beg = g_off[node], end = g_off[node + 1];
    float* p = OUT + (size_t)node * 64 + lane4;
    float4 a0 = *reinterpret_cast<const float4*>(p);
    float4 a1 = make_float4(0.f, 0.f, 0.f, 0.f);
    float4 a2 = make_float4(0.f, 0.f, 0.f, 0.f);
    float4 a3 = make_float4(0.f, 0.f, 0.f, 0.f);
    int j = beg;
    for (; j + 3 < end; j += 4) {
        int2 e0 = __ldg(&g_edge[j + 0]);
        int2 e1 = __ldg(&g_edge[j + 1]);
        int2 e2 = __ldg(&g_edge[j + 2]);
        int2 e3 = __ldg(&g_edge[j + 3]);
        EDGE_FMA(a0, e0, 64) EDGE_FMA(a1, e1, 64)
        EDGE_FMA(a2, e2, 64) EDGE_FMA(a3, e3, 64)
    }
    for (; j < end; j++) {
        int2 e0 = __ldg(&g_edge[j]);
        EDGE_FMA(a0, e0, 64)
    }
    a0.x += a1.x + a2.x + a3.x; a0.y += a1.y + a2.y + a3.y;
    a0.z += a1.z + a2.z + a3.z; a0.w += a1.w + a2.w + a3.w;
    *reinterpret_cast<float4*>(p) = a0;
}

// ---------------------------------------------------------------------------
extern "C" void kernel_launch(void* const* d_in, const int* in_sizes, int n_in,
                              void* d_out, int out_size)
{
    const float* x  = (const float*)d_in[0];
    const int*   ei = (const int*)  d_in[1];
    const float* W1 = (const float*)d_in[2];
    const float* b1 = (const float*)d_in[3];
    const float* W2 = (const float*)d_in[4];
    const float* b2 = (const float*)d_in[5];
    float* out = (float*)d_out;

    const int N = in_sizes[0] / D0;
    const int E = in_sizes[1] / 2;

    float *p_h1, *p_agg1, *p_h2;
    int   *p_degi;
    cudaGetSymbolAddress((void**)&p_h1,   g_h1);
    cudaGetSymbolAddress((void**)&p_agg1, g_agg1);
    cudaGetSymbolAddress((void**)&p_h2,   g_h2);
    cudaGetSymbolAddress((void**)&p_degi, g_degi);

    const int LDBB  = (128 + 8) * 2;
    const int SMEM1 = (64 + 64 + D1 + D1) * LDBB;     // 104448 (TM=64)
    const int SMEM2 = (128 + 128 + D2 + D2) * LDBB;   // 104448 (TM=128)
    cudaFuncSetAttribute(k_mma_gemm<64, D1, false, false, false>,
                         cudaFuncAttributeMaxDynamicSharedMemorySize, SMEM1);
    cudaFuncSetAttribute(k_mma_gemm<128, D2, true, true, true>,
                         cudaFuncAttributeMaxDynamicSharedMemorySize, SMEM2);

    const int nb = (N + SCAN_B - 1) / SCAN_B;

    cudaStream_t s2;
    cudaStreamCreate(&s2);
    cudaEvent_t evF, evCSR, evG1, evB;
    cudaEventCreateWithFlags(&evF,   cudaEventDisableTiming);
    cudaEventCreateWithFlags(&evCSR, cudaEventDisableTiming);
    cudaEventCreateWithFlags(&evG1,  cudaEventDisableTiming);
    cudaEventCreateWithFlags(&evB,   cudaEventDisableTiming);

    cudaEventRecord(evF, 0);
    cudaStreamWaitEvent(s2, evF, 0);

    // branch B (s2): CSR build
    cudaMemsetAsync(p_degi, 0, (size_t)N * sizeof(int), s2);
    k_count_deg       <<<(E / 2 + 255) / 256, 256, 0, s2>>>(ei, E);
    k_dinv_blockreduce<<<nb, SCAN_B, 0, s2>>>(N);
    k_scan_bsum       <<<1, 32, 0, s2>>>(nb);
    k_scan_final      <<<nb, SCAN_B, 0, s2>>>(N, E);
    k_fill            <<<(E / 2 + 255) / 256, 256, 0, s2>>>(ei, E);
    cudaEventRecord(evCSR, s2);

    // branch A (stream 0): pure GEMM1 (TM=64, occupancy 2)
    k_mma_gemm<64, D1, false, false, false><<<(N + 63) / 64, 256, SMEM1, 0>>>(
        x, W1, nullptr, nullptr, p_h1, nullptr, N, 0);
    cudaEventRecord(evG1, 0);

    // join both ways for the chunked tail
    cudaStreamWaitEvent(0, evCSR, 0);
    cudaStreamWaitEvent(s2, evG1, 0);

    // 2-chunk tail: chunk0 on stream 0, chunk1 on s2 (R7 optimum)
    const int half = ((N + 1) / 2 + 127) & ~127;
    const int n0   = half < N ? half : N;
    const int n1   = N - n0;

    k_gather128<<<(n0 + 7) / 8, 256, 0, 0>>>(p_h1, p_agg1, 0, n0);
    k_mma_gemm<128, D2, true, true, true><<<(n0 + 127) / 128, 256, SMEM2, 0>>>(
        p_agg1, W2, b1, b2, p_h2, out, n0, 0);

    if (n1 > 0) {
        k_gather128<<<(n1 + 7) / 8, 256, 0, s2>>>(p_h1, p_agg1, n0, N);
        k_mma_gemm<128, D2, true, true, true><<<(n1 + 127) / 128, 256, SMEM2, s2>>>(
            p_agg1 + (size_t)n0 * D1, W2, b1, b2,
            p_h2 + (size_t)n0 * D2, out + (size_t)n0 * D2, n1, n0);
    }
    cudaEventRecord(evB, s2);

    cudaStreamWaitEvent(0, evB, 0);
    k_gather64<<<(N * 16 + 255) / 256, 256, 0, 0>>>(p_h2, out, N);

    cudaStreamDestroy(s2);
    cudaEventDestroy(evF);
    cudaEventDestroy(evCSR);
    cudaEventDestroy(evG1);
    cudaEventDestroy(evB);
}

// round 14
// speedup vs baseline: 1.1564x; 1.0534x over previous
#include <cuda_runtime.h>
#include <cuda_bf16.h>
#include <cstdint>

#define NN 50000
#define EE 625000
#define D0 128
#define D1 128
#define D2 64
#define SCAN_B 1024
#define NB ((NN + SCAN_B - 1) / SCAN_B)

// ---- device-global scratch ----
__device__ int   g_degi[NN];
__device__ float g_dinv[NN];
__device__ int   g_off [NN + 1];
__device__ int   g_cur [NN];
__device__ int2  g_edge[EE];
__device__ int   g_bsum [NB];
__device__ int   g_bbase[NB];
__device__ float g_h1  [(size_t)NN * D1];
__device__ float g_agg1[(size_t)NN * D1];
__device__ float g_h2  [(size_t)NN * D2];

// ---------------------------------------------------------------------------
// Warp MMA helpers
// ---------------------------------------------------------------------------
__device__ __forceinline__ uint32_t smem_u32(const void* p) {
    uint32_t a;
    asm("{ .reg .u64 t; cvta.to.shared.u64 t, %1; cvt.u32.u64 %0, t; }" : "=r"(a) : "l"(p));
    return a;
}
__device__ __forceinline__ void ldsm_x4(uint32_t* r, uint32_t addr) {
    asm volatile("ldmatrix.sync.aligned.m8n8.x4.shared.b16 {%0,%1,%2,%3}, [%4];"
                 : "=r"(r[0]), "=r"(r[1]), "=r"(r[2]), "=r"(r[3]) : "r"(addr));
}
__device__ __forceinline__ void mma_bf16(float* d, const uint32_t* a, const uint32_t* b) {
    asm volatile(
        "mma.sync.aligned.m16n8k16.row.col.f32.bf16.bf16.f32 "
        "{%0,%1,%2,%3}, {%4,%5,%6,%7}, {%8,%9}, {%0,%1,%2,%3};"
        : "+f"(d[0]), "+f"(d[1]), "+f"(d[2]), "+f"(d[3])
        : "r"(a[0]), "r"(a[1]), "r"(a[2]), "r"(a[3]), "r"(b[0]), "r"(b[1]));
}
__device__ __forceinline__ void bf16_split(float x, __nv_bfloat16& h, __nv_bfloat16& l) {
    h = __float2bfloat16_rn(x);
    l = __float2bfloat16_rn(x - __bfloat162float(h));
}

// ---------------------------------------------------------------------------
// CSR build — scalar 1-edge/thread (max TLP; vectorized variants regressed)
// ---------------------------------------------------------------------------
__global__ void k_count_deg(const int* __restrict__ ei, int E) {
    int e = blockIdx.x * blockDim.x + threadIdx.x;
    if (e < E) atomicAdd(&g_degi[ei[E + e]], 1);
}

__global__ void k_dinv_blockreduce(int N) {
    __shared__ int warp_sum[32];
    int i = blockIdx.x * SCAN_B + threadIdx.x;
    int v = 0;
    if (i < N) {
        v = g_degi[i];
        g_dinv[i] = rsqrtf((float)(v + 1));
    }
    int s = v;
    #pragma unroll
    for (int o = 16; o > 0; o >>= 1) s += __shfl_down_sync(0xffffffffu, s, o);
    if ((threadIdx.x & 31) == 0) warp_sum[threadIdx.x >> 5] = s;
    __syncthreads();
    if (threadIdx.x < 32) {
        int t = (threadIdx.x < (SCAN_B / 32)) ? warp_sum[threadIdx.x] : 0;
        #pragma unroll
        for (int o = 16; o > 0; o >>= 1) t += __shfl_down_sync(0xffffffffu, t, o);
        if (threadIdx.x == 0) g_bsum[blockIdx.x] = t;
    }
}

__global__ void k_scan_bsum(int B) {
    int lane = threadIdx.x;
    int i0 = 2 * lane, i1 = 2 * lane + 1;
    int v0 = (i0 < B) ? g_bsum[i0] : 0;
    int v1 = (i1 < B) ? g_bsum[i1] : 0;
    int p = v0 + v1;
    int s = p;
    #pragma unroll
    for (int o = 1; o < 32; o <<= 1) {
        int u = __shfl_up_sync(0xffffffffu, s, o);
        if (lane >= o) s += u;
    }
    int ex = s - p;
    if (i0 < B) g_bbase[i0] = ex;
    if (i1 < B) g_bbase[i1] = ex + v0;
}

// warp-shfl block scan (2 barriers; measured faster than Hillis-Steele)
__global__ void k_scan_final(int N, int E) {
    __shared__ int wsum[32];
    int t = threadIdx.x;
    int lane = t & 31, w = t >> 5;
    int i = blockIdx.x * SCAN_B + t;
    int v = (i < N) ? g_degi[i] : 0;
    int s = v;
    #pragma unroll
    for (int o = 1; o < 32; o <<= 1) {
        int u = __shfl_up_sync(0xffffffffu, s, o);
        if (lane >= o) s += u;
    }
    if (lane == 31) wsum[w] = s;
    __syncthreads();
    if (w == 0) {
        int ws = wsum[lane];
        #pragma unroll
        for (int o = 1; o < 32; o <<= 1) {
            int u = __shfl_up_sync(0xffffffffu, ws, o);
            if (lane >= o) ws += u;
        }
        wsum[lane] = ws;
    }
    __syncthreads();
    int base = (w > 0) ? wsum[w - 1] : 0;
    if (i < N) {
        int ex = g_bbase[blockIdx.x] + base + s - v;
        g_off[i] = ex;
        g_cur[i] = ex;
        if (i == N - 1) g_off[N] = E;
    }
}

__global__ void k_fill(const int* __restrict__ ei, int E) {
    int e = blockIdx.x * blockDim.x + threadIdx.x;
    if (e >= E) return;
    int s = __ldg(ei + e);
    int d = __ldg(ei + E + e);
    int p = atomicAdd(&g_cur[d], 1);
    g_edge[p] = make_int2(s, __float_as_int(g_dinv[s] * g_dinv[d]));
}

// ---------------------------------------------------------------------------
// Tensor-core GEMM (bf16 hi/lo split, fp32 acc), occupancy 2.
// ---------------------------------------------------------------------------
template <int TM, int NOUT, bool IN_ACT, bool OUT_BIAS, bool WRITE_AGG>
__global__ __launch_bounds__(256, 2)
void k_mma_gemm(const float* __restrict__ A, const float* __restrict__ W,
                const float* __restrict__ bin, const float* __restrict__ bout,
                float* __restrict__ H, float* __restrict__ AGG, int M, int row_base)
{
    constexpr int K   = 128;
    constexpr int LDB = (K + 8) * 2;
    constexpr uint32_t OFF_AHI = 0;
    constexpr uint32_t OFF_ALO = OFF_AHI + TM * LDB;
    constexpr uint32_t OFF_WHI = OFF_ALO + TM * LDB;
    constexpr uint32_t OFF_WLO = OFF_WHI + NOUT * LDB;
    constexpr int MW = TM / 32;
    constexpr int NW = 8 / MW;
    constexpr int WN = NOUT / NW;
    constexpr int NT = WN / 8;
    constexpr int NG = NT / 2;

    extern __shared__ char smem[];
    const uint32_t sb = smem_u32(smem);
    const int tid    = threadIdx.x;
    const int wid    = tid >> 5;
    const int lane   = tid & 31;
    const int warp_m = wid & (MW - 1);
    const int warp_n = wid / MW;
    const int row0   = blockIdx.x * TM;

    for (int fid = tid; fid < TM * (K / 4); fid += 256) {
        int r = fid >> 5, k = (fid & 31) * 4;
        int row = row0 + r;
        float4 v = make_float4(0.f, 0.f, 0.f, 0.f);
        if (row < M)
            v = *reinterpret_cast<const float4*>(A + (size_t)row * K + k);
        if (IN_ACT) {
            v.x = fmaxf(v.x + __ldg(bin + k + 0), 0.f);
            v.y = fmaxf(v.y + __ldg(bin + k + 1), 0.f);
            v.z = fmaxf(v.z + __ldg(bin + k + 2), 0.f);
            v.w = fmaxf(v.w + __ldg(bin + k + 3), 0.f);
        }
        __nv_bfloat162 h01, h23, l01, l23;
        bf16_split(v.x, h01.x, l01.x); bf16_split(v.y, h01.y, l01.y);
        bf16_split(v.z, h23.x, l23.x); bf16_split(v.w, h23.y, l23.y);
        uint32_t o = (uint32_t)r * LDB + (uint32_t)k * 2;
        *reinterpret_cast<uint2*>(smem + OFF_AHI + o) =
            make_uint2(*reinterpret_cast<uint32_t*>(&h01), *reinterpret_cast<uint32_t*>(&h23));
        *reinterpret_cast<uint2*>(smem + OFF_ALO + o) =
            make_uint2(*reinterpret_cast<uint32_t*>(&l01), *reinterpret_cast<uint32_t*>(&l23));
    }
    for (int fid = tid; fid < NOUT * (K / 4); fid += 256) {
        int c = fid >> 5, k = (fid & 31) * 4;
        float4 v = *reinterpret_cast<const float4*>(W + (size_t)c * K + k);
        __nv_bfloat162 h01, h23, l01, l23;
        bf16_split(v.x, h01.x, l01.x); bf16_split(v.y, h01.y, l01.y);
        bf16_split(v.z, h23.x, l23.x); bf16_split(v.w, h23.y, l23.y);
        uint32_t o = (uint32_t)c * LDB + (uint32_t)k * 2;
        *reinterpret_cast<uint2*>(smem + OFF_WHI + o) =
            make_uint2(*reinterpret_cast<uint32_t*>(&h01), *reinterpret_cast<uint32_t*>(&h23));
        *reinterpret_cast<uint2*>(smem + OFF_WLO + o) =
            make_uint2(*reinterpret_cast<uint32_t*>(&l01), *reinterpret_cast<uint32_t*>(&l23));
    }
    __syncthreads();

    float acc[2][NT][4];
    #pragma unroll
    for (int mt = 0; mt < 2; mt++)
        #pragma unroll
        for (int nt = 0; nt < NT; nt++)
            #pragma unroll
            for (int j = 0; j < 4; j++) acc[mt][nt][j] = 0.f;

    const uint32_t a_roff = (uint32_t)((lane & 7) + ((lane >> 3) & 1) * 8) * LDB
                          + (uint32_t)((lane >> 4) * 8) * 2;
    const uint32_t b_roff = (uint32_t)((lane & 7) + ((lane >> 4) & 1) * 8) * LDB
                          + (uint32_t)(((lane >> 3) & 1) * 8) * 2;

    #pragma unroll
    for (int ks = 0; ks < K / 16; ks++) {
        const uint32_t kb = (uint32_t)(ks * 16) * 2;
        uint32_t ah[2][4], al[2][4];
        #pragma unroll
        for (int mt = 0; mt < 2; mt++) {
            uint32_t base = (uint32_t)(warp_m * 32 + mt * 16) * LDB + kb + a_roff;
            ldsm_x4(ah[mt], sb + OFF_AHI + base);
            ldsm_x4(al[mt], sb + OFF_ALO + base);
        }
        uint32_t bh[NG][4], bl[NG][4];
        #pragma unroll
        for (int g = 0; g < NG; g++) {
            uint32_t base = (uint32_t)(warp_n * WN + g * 16) * LDB + kb + b_roff;
            ldsm_x4(bh[g], sb + OFF_WHI + base);
            ldsm_x4(bl[g], sb + OFF_WLO + base);
        }
        #pragma unroll
        for (int mt = 0; mt < 2; mt++)
            #pragma unroll
            for (int nt = 0; nt < NT; nt++) {
                const uint32_t* ph = &bh[nt >> 1][(nt & 1) * 2];
                const uint32_t* pl = &bl[nt >> 1][(nt & 1) * 2];
                mma_bf16(acc[mt][nt], ah[mt], ph);
                mma_bf16(acc[mt][nt], ah[mt], pl);
                mma_bf16(acc[mt][nt], al[mt], ph);
            }
    }

    #pragma unroll
    for (int mt = 0; mt < 2; mt++) {
        int rbase = row0 + warp_m * 32 + mt * 16 + (lane >> 2);
        #pragma unroll
        for (int hf = 0; hf < 2; hf++) {
            int row = rbase + hf * 8;
            if (row < M) {
                float s = 0.f;
                if (WRITE_AGG) { s = g_dinv[row_base + row]; s = s * s; }
                #pragma unroll
                for (int nt = 0; nt < NT; nt++) {
                    int c = warp_n * WN + nt * 8 + (lane & 3) * 2;
                    float2 hv = make_float2(acc[mt][nt][hf * 2 + 0], acc[mt][nt][hf * 2 + 1]);
                    *reinterpret_cast<float2*>(H + (size_t)row * NOUT + c) = hv;
                    if (WRITE_AGG) {
                        float2 av;
                        if (OUT_BIAS) {
                            av.x = fmaf(s, hv.x, __ldg(bout + c + 0));
                            av.y = fmaf(s, hv.y, __ldg(bout + c + 1));
                        } else {
                            av = make_float2(s * hv.x, s * hv.y);
                        }
                        *reinterpret_cast<float2*>(AGG + (size_t)row * NOUT + c) = av;
                    }
                }
            }
        }
    }
}

// ---------------------------------------------------------------------------
// CSR gathers (chunked on node range)
// ---------------------------------------------------------------------------
#define EDGE_FMA(a, e, width)                                                     \
    {                                                                             \
        float c_ = __int_as_float((e).y);                                         \
        const float4 v_ = *reinterpret_cast<const float4*>(                       \
            H + (size_t)(e).x * (width) + lane4);                                 \
        (a).x = fmaf(c_, v_.x, (a).x); (a).y = fmaf(c_, v_.y, (a).y);             \
        (a).z = fmaf(c_, v_.z, (a).z); (a).w = fmaf(c_, v_.w, (a).w);             \
    }

__global__ void k_gather128(const float* __restrict__ H, float* __restrict__ AGG,
                            int node_beg, int node_end)
{
    int node = node_beg + blockIdx.x * (blockDim.x >> 5) + (threadIdx.x >> 5);
    int lane4 = (threadIdx.x & 31) * 4;
    if (node >= node_end) return;
    int beg = g_off[node], end = g_off[node + 1];
    float s = g_dinv[node]; s = s * s;
    float4 hs = *reinterpret_cast<const float4*>(H + (size_t)node * 128 + lane4);
    float4 a0 = make_float4(s * hs.x, s * hs.y, s * hs.z, s * hs.w);
    float4 a1 = make_float4(0.f, 0.f, 0.f, 0.f);
    float4 a2 = make_float4(0.f, 0.f, 0.f, 0.f);
    float4 a3 = make_float4(0.f, 0.f, 0.f, 0.f);
    int j = beg;
    for (; j + 3 < end; j += 4) {
        int2 e0 = __ldg(&g_edge[j + 0]);
        int2 e1 = __ldg(&g_edge[j + 1]);
        int2 e2 = __ldg(&g_edge[j + 2]);
        int2 e3 = __ldg(&g_edge[j + 3]);
        EDGE_FMA(a0, e0, 128) EDGE_FMA(a1, e1, 128)
        EDGE_FMA(a2, e2, 128) EDGE_FMA(a3, e3, 128)
    }
    for (; j < end; j++) {
        int2 e0 = __ldg(&g_edge[j]);
        EDGE_FMA(a0, e0, 128)
    }
    a0.x += a1.x + a2.x + a3.x; a0.y += a1.y + a2.y + a3.y;
    a0.z += a1.z + a2.z + a3.z; a0.w += a1.w + a2.w + a3.w;
    *reinterpret_cast<float4*>(AGG + (size_t)node * 128 + lane4) = a0;
}

__global__ void k_gather64(const float* __restrict__ H, float* __restrict__ OUT, int N)
{
    int idx  = blockIdx.x * blockDim.x + threadIdx.x;
    int node = idx >> 4;
    int lane4 = (idx & 15) * 4;
    if (node >= N) return;
    int beg = g_off[node], end = g_off[node + 1];
    float* p = OUT + (size_t)node * 64 + lane4;
    float4 a0 = *reinterpret_cast<const float4*>(p);
    float4 a1 = make_float4(0.f, 0.f, 0.f, 0.f);
    float4 a2 = make_float4(0.f, 0.f, 0.f, 0.f);
    float4 a3 = make_float4(0.f, 0.f, 0.f, 0.f);
    int j = beg;
    for (; j + 3 < end; j += 4) {
        int2 e0 = __ldg(&g_edge[j + 0]);
        int2 e1 = __ldg(&g_edge[j + 1]);
        int2 e2 = __ldg(&g_edge[j + 2]);
        int2 e3 = __ldg(&g_edge[j + 3]);
        EDGE_FMA(a0, e0, 64) EDGE_FMA(a1, e1, 64)
        EDGE_FMA(a2, e2, 64) EDGE_FMA(a3, e3, 64)
    }
    for (; j < end; j++) {
        int2 e0 = __ldg(&g_edge[j]);
        EDGE_FMA(a0, e0, 64)
    }
    a0.x += a1.x + a2.x + a3.x; a0.y += a1.y + a2.y + a3.y;
    a0.z += a1.z + a2.z + a3.z; a0.w += a1.w + a2.w + a3.w;
    *reinterpret_cast<float4*>(p) = a0;
}

// ---------------------------------------------------------------------------
extern "C" void kernel_launch(void* const* d_in, const int* in_sizes, int n_in,
                              void* d_out, int out_size)
{
    const float* x  = (const float*)d_in[0];
    const int*   ei = (const int*)  d_in[1];
    const float* W1 = (const float*)d_in[2];
    const float* b1 = (const float*)d_in[3];
    const float* W2 = (const float*)d_in[4];
    const float* b2 = (const float*)d_in[5];
    float* out = (float*)d_out;

    const int N = in_sizes[0] / D0;
    const int E = in_sizes[1] / 2;

    float *p_h1, *p_agg1, *p_h2;
    int   *p_degi;
    cudaGetSymbolAddress((void**)&p_h1,   g_h1);
    cudaGetSymbolAddress((void**)&p_agg1, g_agg1);
    cudaGetSymbolAddress((void**)&p_h2,   g_h2);
    cudaGetSymbolAddress((void**)&p_degi, g_degi);

    const int LDBB  = (128 + 8) * 2;
    const int SMEM1 = (64 + 64 + D1 + D1) * LDBB;     // 104448 (TM=64)
    const int SMEM2 = (128 + 128 + D2 + D2) * LDBB;   // 104448 (TM=128)
    cudaFuncSetAttribute(k_mma_gemm<64, D1, false, false, false>,
                         cudaFuncAttributeMaxDynamicSharedMemorySize, SMEM1);
    cudaFuncSetAttribute(k_mma_gemm<128, D2, true, true, true>,
                         cudaFuncAttributeMaxDynamicSharedMemorySize, SMEM2);

    const int nb = (N + SCAN_B - 1) / SCAN_B;

    cudaStream_t s2;
    cudaStreamCreate(&s2);
    cudaEvent_t evF, evCSR, evG1, evB;
    cudaEventCreateWithFlags(&evF,   cudaEventDisableTiming);
    cudaEventCreateWithFlags(&evCSR, cudaEventDisableTiming);
    cudaEventCreateWithFlags(&evG1,  cudaEventDisableTiming);
    cudaEventCreateWithFlags(&evB,   cudaEventDisableTiming);

    cudaEventRecord(evF, 0);
    cudaStreamWaitEvent(s2, evF, 0);

    // branch B (s2): CSR build (scalar count/fill — max TLP)
    cudaMemsetAsync(p_degi, 0, (size_t)N * sizeof(int), s2);
    k_count_deg       <<<(E + 255) / 256, 256, 0, s2>>>(ei, E);
    k_dinv_blockreduce<<<nb, SCAN_B, 0, s2>>>(N);
    k_scan_bsum       <<<1, 32, 0, s2>>>(nb);
    k_scan_final      <<<nb, SCAN_B, 0, s2>>>(N, E);
    k_fill            <<<(E + 255) / 256, 256, 0, s2>>>(ei, E);
    cudaEventRecord(evCSR, s2);

    // branch A (stream 0): pure GEMM1 (TM=64, occupancy 2)
    k_mma_gemm<64, D1, false, false, false><<<(N + 63) / 64, 256, SMEM1, 0>>>(
        x, W1, nullptr, nullptr, p_h1, nullptr, N, 0);
    cudaEventRecord(evG1, 0);

    // join both ways for the chunked tail
    cudaStreamWaitEvent(0, evCSR, 0);
    cudaStreamWaitEvent(s2, evG1, 0);

    // 2-chunk tail: chunk0 on stream 0, chunk1 on s2 (R7 optimum)
    const int half = ((N + 1) / 2 + 127) & ~127;
    const int n0   = half < N ? half : N;
    const int n1   = N - n0;

    k_gather128<<<(n0 + 7) / 8, 256, 0, 0>>>(p_h1, p_agg1, 0, n0);
    k_mma_gemm<128, D2, true, true, true><<<(n0 + 127) / 128, 256, SMEM2, 0>>>(
        p_agg1, W2, b1, b2, p_h2, out, n0, 0);

    if (n1 > 0) {
        k_gather128<<<(n1 + 7) / 8, 256, 0, s2>>>(p_h1, p_agg1, n0, N);
        k_mma_gemm<128, D2, true, true, true><<<(n1 + 127) / 128, 256, SMEM2, s2>>>(
            p_agg1 + (size_t)n0 * D1, W2, b1, b2,
            p_h2 + (size_t)n0 * D2, out + (size_t)n0 * D2, n1, n0);
    }
    cudaEventRecord(evB, s2);

    cudaStreamWaitEvent(0, evB, 0);
    k_gather64<<<(N * 16 + 255) / 256, 256, 0, 0>>>(p_h2, out, N);

    cudaStreamDestroy(s2);
    cudaEventDestroy(evF);
    cudaEventDestroy(evCSR);
    cudaEventDestroy(evG1);
    cudaEventDestroy(evB);
}